// round 1
// baseline (speedup 1.0000x reference)
#include <cuda_runtime.h>

#define NN 50000
#define HH 128
#define RR 6
#define EE 800000
#define LL 3
#define KK 3

// ---------------- static device scratch (no allocations allowed) ----------------
__device__ __align__(16) static float g_emb[(size_t)RR * NN * HH];   // 153.6 MB
__device__ __align__(16) static float g_hA[(size_t)NN * HH];
__device__ __align__(16) static float g_hB[(size_t)NN * HH];
__device__ __align__(16) static float g_tx[(size_t)NN * HH];
__device__ __align__(16) static float g_tx2[(size_t)NN * HH];
__device__ static int   g_deg[RR * NN];
__device__ static int   g_cnt[RR * NN];
__device__ static int   g_rp[RR * NN + 1];
__device__ static int   g_cur[RR * NN];
__device__ static int   g_col[RR * EE];
__device__ static float g_dinv[RR * NN];
__device__ static int   g_bsums[1024];

// ---------------- CSR build ----------------
__global__ void zero2_kernel(int* a, int* b, int n) {
    int i = blockIdx.x * blockDim.x + threadIdx.x;
    if (i < n) { a[i] = 0; b[i] = 0; }
}

__global__ void count_kernel(const int* __restrict__ ei, int* __restrict__ deg,
                             int* __restrict__ cnt) {
    int idx = blockIdx.x * blockDim.x + threadIdx.x;
    if (idx >= RR * EE) return;
    int r = idx / EE;
    int e = idx - r * EE;
    int src = ei[(size_t)r * 2 * EE + e];
    int dst = ei[(size_t)r * 2 * EE + EE + e];
    atomicAdd(&deg[r * NN + src], 1);   // out-degree (reference counts at src)
    atomicAdd(&cnt[r * NN + dst], 1);   // in-degree for CSR-by-dst
}

__global__ void dinv_kernel(const int* __restrict__ deg, float* __restrict__ dinv) {
    int i = blockIdx.x * blockDim.x + threadIdx.x;
    if (i >= RR * NN) return;
    int d = deg[i];
    dinv[i] = (d > 0) ? rsqrtf((float)d) : 0.0f;
}

// exclusive scan, 3 phases (n = R*N = 300000, nb = 293 blocks of 1024)
__global__ void scan1_kernel(const int* __restrict__ in, int* __restrict__ out,
                             int* __restrict__ bsums, int n) {
    __shared__ int sh[1024];
    int i = blockIdx.x * 1024 + threadIdx.x;
    int v = (i < n) ? in[i] : 0;
    sh[threadIdx.x] = v;
    __syncthreads();
    for (int off = 1; off < 1024; off <<= 1) {
        int t = (threadIdx.x >= off) ? sh[threadIdx.x - off] : 0;
        __syncthreads();
        sh[threadIdx.x] += t;
        __syncthreads();
    }
    if (i < n) out[i] = sh[threadIdx.x] - v;          // exclusive within block
    if (threadIdx.x == 1023) bsums[blockIdx.x] = sh[1023];
}

__global__ void scan2_kernel(int* bsums, int nb) {
    __shared__ int sh[512];
    int v = (threadIdx.x < nb) ? bsums[threadIdx.x] : 0;
    sh[threadIdx.x] = v;
    __syncthreads();
    for (int off = 1; off < 512; off <<= 1) {
        int t = (threadIdx.x >= off) ? sh[threadIdx.x - off] : 0;
        __syncthreads();
        sh[threadIdx.x] += t;
        __syncthreads();
    }
    if (threadIdx.x < nb) bsums[threadIdx.x] = sh[threadIdx.x] - v;  // exclusive
}

__global__ void scan3_kernel(int* __restrict__ rp, const int* __restrict__ bsums,
                             int* __restrict__ cur, int n, int total) {
    int i = blockIdx.x * 1024 + threadIdx.x;
    if (i < n) {
        int v = rp[i] + bsums[blockIdx.x];
        rp[i] = v;
        cur[i] = v;
    }
    if (i == 0) rp[n] = total;
}

__global__ void fill_kernel(const int* __restrict__ ei, int* __restrict__ cur,
                            int* __restrict__ col) {
    int idx = blockIdx.x * blockDim.x + threadIdx.x;
    if (idx >= RR * EE) return;
    int r = idx / EE;
    int e = idx - r * EE;
    int src = ei[(size_t)r * 2 * EE + e];
    int dst = ei[(size_t)r * 2 * EE + EE + e];
    int pos = atomicAdd(&cur[r * NN + dst], 1);       // global position in combined col
    col[pos] = src;
}

// ---------------- sparse propagation ----------------
// out[n,:] = -alpha * dinv[n] * sum_{e in row n} dinv[src_e] * hin[src_e,:]  ( - sub[n,:] )
__global__ void prop_kernel(const float4* __restrict__ hin, float4* __restrict__ hout,
                            const int* __restrict__ rowptr, const int* __restrict__ col,
                            const float* __restrict__ dinv, const float4* __restrict__ sub,
                            float alpha) {
    int t = blockIdx.x * blockDim.x + threadIdx.x;
    int w = t >> 5;
    int lane = t & 31;
    if (w >= NN) return;
    int e = rowptr[w];
    int e1 = rowptr[w + 1];
    float4 acc = make_float4(0.f, 0.f, 0.f, 0.f);
    for (; e + 1 < e1; e += 2) {
        int sa = __ldg(&col[e]);
        int sb = __ldg(&col[e + 1]);
        float wa = __ldg(&dinv[sa]);
        float wb = __ldg(&dinv[sb]);
        float4 va = hin[(size_t)sa * 32 + lane];
        float4 vb = hin[(size_t)sb * 32 + lane];
        acc.x += wa * va.x + wb * vb.x;
        acc.y += wa * va.y + wb * vb.y;
        acc.z += wa * va.z + wb * vb.z;
        acc.w += wa * va.w + wb * vb.w;
    }
    if (e < e1) {
        int sa = __ldg(&col[e]);
        float wa = __ldg(&dinv[sa]);
        float4 va = hin[(size_t)sa * 32 + lane];
        acc.x += wa * va.x;
        acc.y += wa * va.y;
        acc.z += wa * va.z;
        acc.w += wa * va.w;
    }
    float sc = -alpha * dinv[w];
    float4 r;
    r.x = sc * acc.x; r.y = sc * acc.y; r.z = sc * acc.z; r.w = sc * acc.w;
    if (sub) {
        float4 u = sub[(size_t)w * 32 + lane];
        r.x -= u.x; r.y -= u.y; r.z -= u.z; r.w -= u.w;
    }
    hout[(size_t)w * 32 + lane] = r;
}

// ---------------- segmented SGEMM: C[N,128] = relu( sum_s Aseg[s][N,128] @ B[s*128.., 128] + bias ) ---
struct Seg { const float* p[6]; };

__global__ __launch_bounds__(256, 2)
void gemm_kernel(Seg A, int nseg, const float* __restrict__ B,
                 const float* __restrict__ bias, float* __restrict__ C, int relu) {
    __shared__ float As[32][129];   // transposed [k][m], pad -> conflict-free
    __shared__ float Bs[32][128];
    const int K = nseg * 128;
    const int bm = blockIdx.x * 128;
    const int tid = threadIdx.x;
    const int tx = tid & 15;        // output col group (8 cols)
    const int ty = tid >> 4;        // output row group (8 rows)

    float acc[8][8];
#pragma unroll
    for (int i = 0; i < 8; i++)
#pragma unroll
        for (int j = 0; j < 8; j++) acc[i][j] = 0.f;

    for (int k0 = 0; k0 < K; k0 += 32) {
        const float* Ap = A.p[k0 >> 7];
        const int klocal = k0 & 127;
        // A tile: 128 rows x 32 k, float4 along k, store transposed
#pragma unroll
        for (int i = 0; i < 4; i++) {
            int li = i * 256 + tid;
            int m = li >> 3;
            int kq = (li & 7) << 2;
            int gm = bm + m;
            float4 v = make_float4(0.f, 0.f, 0.f, 0.f);
            if (gm < NN) v = *(const float4*)(Ap + (size_t)gm * HH + klocal + kq);
            As[kq + 0][m] = v.x;
            As[kq + 1][m] = v.y;
            As[kq + 2][m] = v.z;
            As[kq + 3][m] = v.w;
        }
        // B tile: 32 k x 128 cols
#pragma unroll
        for (int i = 0; i < 4; i++) {
            int li = i * 256 + tid;
            int kb = li >> 5;
            int nb = (li & 31) << 2;
            *(float4*)&Bs[kb][nb] = *(const float4*)(B + (size_t)(k0 + kb) * HH + nb);
        }
        __syncthreads();
#pragma unroll
        for (int k = 0; k < 32; k++) {
            float a[8], b[8];
#pragma unroll
            for (int i = 0; i < 8; i++) a[i] = As[k][ty * 8 + i];
#pragma unroll
            for (int j = 0; j < 8; j++) b[j] = Bs[k][tx * 8 + j];
#pragma unroll
            for (int i = 0; i < 8; i++)
#pragma unroll
                for (int j = 0; j < 8; j++) acc[i][j] += a[i] * b[j];
        }
        __syncthreads();
    }

    float bi[8];
#pragma unroll
    for (int j = 0; j < 8; j++) bi[j] = bias[tx * 8 + j];
#pragma unroll
    for (int i = 0; i < 8; i++) {
        int gm = bm + ty * 8 + i;
        if (gm < NN) {
            float v[8];
#pragma unroll
            for (int j = 0; j < 8; j++) {
                v[j] = acc[i][j] + bi[j];
                if (relu) v[j] = fmaxf(v[j], 0.f);
            }
            float* cp = C + (size_t)gm * HH + tx * 8;
            *(float4*)cp = make_float4(v[0], v[1], v[2], v[3]);
            *(float4*)(cp + 4) = make_float4(v[4], v[5], v[6], v[7]);
        }
    }
}

// ---------------- final: logit + aux (H->1 dots), one warp per output ----------------
__global__ void final_kernel(const float4* __restrict__ hc, const float4* __restrict__ emb,
                             const float* __restrict__ clsW2, const float* __restrict__ clsb2,
                             const float* __restrict__ auxW, const float* __restrict__ auxB,
                             float* __restrict__ out) {
    int t = blockIdx.x * blockDim.x + threadIdx.x;
    int gw = t >> 5;
    int lane = t & 31;
    if (gw >= (RR + 1) * NN) return;
    const float4* vec;
    const float4* wv;
    float b;
    if (gw < NN) {
        vec = hc + (size_t)gw * 32;
        wv = (const float4*)clsW2;
        b = clsb2[0];
    } else {
        int r = (gw - NN) / NN;
        int n = (gw - NN) - r * NN;
        vec = emb + ((size_t)r * NN + n) * 32;
        wv = (const float4*)(auxW + r * HH);
        b = auxB[r];
    }
    float4 a = vec[lane];
    float4 w = wv[lane];
    float s = a.x * w.x + a.y * w.y + a.z * w.z + a.w * w.w;
#pragma unroll
    for (int off = 16; off; off >>= 1) s += __shfl_xor_sync(0xFFFFFFFFu, s, off);
    if (lane == 0) out[gw] = s + b;   // out layout: [logit(N) | aux(R,N)] -> index == gw
}

// ---------------- launch ----------------
extern "C" void kernel_launch(void* const* d_in, const int* in_sizes, int n_in,
                              void* d_out, int out_size) {
    (void)in_sizes; (void)n_in; (void)out_size;
    const float* x     = (const float*)d_in[0];
    const int*   ei    = (const int*)d_in[1];
    const float* chebW = (const float*)d_in[2];
    const float* chebB = (const float*)d_in[3];
    const float* projW = (const float*)d_in[4];
    const float* projB = (const float*)d_in[5];
    const float* W1    = (const float*)d_in[6];
    const float* b1    = (const float*)d_in[7];
    const float* W2    = (const float*)d_in[8];
    const float* b2    = (const float*)d_in[9];
    const float* auxW  = (const float*)d_in[10];
    const float* auxB  = (const float*)d_in[11];
    float* out = (float*)d_out;

    float *emb, *hA, *hB, *tx, *tx2, *dinv;
    int *deg, *cnt, *rp, *cur, *col, *bs;
    cudaGetSymbolAddress((void**)&emb, g_emb);
    cudaGetSymbolAddress((void**)&hA, g_hA);
    cudaGetSymbolAddress((void**)&hB, g_hB);
    cudaGetSymbolAddress((void**)&tx, g_tx);
    cudaGetSymbolAddress((void**)&tx2, g_tx2);
    cudaGetSymbolAddress((void**)&dinv, g_dinv);
    cudaGetSymbolAddress((void**)&deg, g_deg);
    cudaGetSymbolAddress((void**)&cnt, g_cnt);
    cudaGetSymbolAddress((void**)&rp, g_rp);
    cudaGetSymbolAddress((void**)&cur, g_cur);
    cudaGetSymbolAddress((void**)&col, g_col);
    cudaGetSymbolAddress((void**)&bs, g_bsums);

    // CSR build (every call; deterministic up to within-row order -> fp32 ULPs)
    zero2_kernel<<<(RR * NN + 255) / 256, 256>>>(deg, cnt, RR * NN);
    count_kernel<<<(RR * EE + 255) / 256, 256>>>(ei, deg, cnt);
    dinv_kernel<<<(RR * NN + 255) / 256, 256>>>(deg, dinv);
    const int ntot = RR * NN;
    const int nb = (ntot + 1023) / 1024;   // 293
    scan1_kernel<<<nb, 1024>>>(cnt, rp, bs, ntot);
    scan2_kernel<<<1, 512>>>(bs, nb);
    scan3_kernel<<<nb, 1024>>>(rp, bs, cur, ntot, RR * EE);
    fill_kernel<<<(RR * EE + 255) / 256, 256>>>(ei, cur, col);

    const int propBlocks = (NN * 32 + 255) / 256;
    const int gemmGrid = (NN + 127) / 128;

    for (int r = 0; r < RR; r++) {
        const float* h = x;
        for (int l = 0; l < LL; l++) {
            // Tx = P h
            prop_kernel<<<propBlocks, 256>>>((const float4*)h, (float4*)tx,
                                             rp + r * NN, col, dinv + r * NN, nullptr, 1.0f);
            // Tx2 = 2 P Tx - h
            prop_kernel<<<propBlocks, 256>>>((const float4*)tx, (float4*)tx2,
                                             rp + r * NN, col, dinv + r * NN,
                                             (const float4*)h, 2.0f);
            float* o = (l == LL - 1) ? (emb + (size_t)r * NN * HH) : (l == 0 ? hA : hB);
            Seg s;
            s.p[0] = h; s.p[1] = tx; s.p[2] = tx2;
            s.p[3] = nullptr; s.p[4] = nullptr; s.p[5] = nullptr;
            gemm_kernel<<<gemmGrid, 256>>>(s, 3,
                                           chebW + (size_t)(r * LL + l) * KK * HH * HH,
                                           chebB + (size_t)(r * LL + l) * HH, o, 1);
            h = o;
        }
    }

    // hp = relu(concat_r(emb) @ projW + projB)
    Seg sp;
    for (int r = 0; r < RR; r++) sp.p[r] = emb + (size_t)r * NN * HH;
    gemm_kernel<<<gemmGrid, 256>>>(sp, 6, projW, projB, hA, 1);

    // hc = relu(hp @ W1 + b1)
    Seg s1;
    s1.p[0] = hA;
    for (int i = 1; i < 6; i++) s1.p[i] = nullptr;
    gemm_kernel<<<gemmGrid, 256>>>(s1, 1, W1, b1, hB, 1);

    // logit + aux
    final_kernel<<<((RR + 1) * NN * 32 + 255) / 256, 256>>>(
        (const float4*)hB, (const float4*)emb, W2, b2, auxW, auxB, out);
}

// round 3
// speedup vs baseline: 1.4088x; 1.4088x over previous
#include <cuda_runtime.h>
#include <cuda_bf16.h>
#include <cstdint>

#define NN 50000
#define HH 128
#define RR 6
#define EE 800000
#define LL 3
#define KK 3

// total B chunks: 18 cheb GEMMs * 6 + proj 12 + cls1 2 = 122
#define NCH_TOTAL 122

// ---------------- static device scratch ----------------
__device__ __align__(16) static float g_emb[(size_t)RR * NN * HH];
__device__ __align__(16) static float g_hA[(size_t)NN * HH];
__device__ __align__(16) static float g_hB[(size_t)NN * HH];
__device__ __align__(16) static float g_tx[(size_t)NN * HH];
__device__ __align__(16) static float g_tx2[(size_t)NN * HH];
__device__ static int   g_deg[RR * NN];
__device__ static int   g_cnt[RR * NN];
__device__ static int   g_rp[RR * NN + 1];
__device__ static int   g_cur[RR * NN];
__device__ static int   g_col[RR * EE];
__device__ static float g_dinv[RR * NN];
__device__ static int   g_bsums[1024];
// pre-swizzled bf16 weight tile images: [chunk][8192] (16KB each)
__device__ __align__(16) static __nv_bfloat16 g_Bhi[(size_t)NCH_TOTAL * 8192];
__device__ __align__(16) static __nv_bfloat16 g_Blo[(size_t)NCH_TOTAL * 8192];

#define SW128(off) ((off) ^ (((off) >> 3) & 0x70))

__device__ __forceinline__ uint32_t smem_u32(const void* p) {
    uint32_t a;
    asm("{ .reg .u64 t; cvta.to.shared.u64 t, %1; cvt.u32.u64 %0, t; }" : "=r"(a) : "l"(p));
    return a;
}
__device__ __forceinline__ void ldsm4(uint32_t* r, uint32_t addr) {
    asm volatile("ldmatrix.sync.aligned.m8n8.x4.shared.b16 {%0,%1,%2,%3}, [%4];"
                 : "=r"(r[0]), "=r"(r[1]), "=r"(r[2]), "=r"(r[3]) : "r"(addr));
}
__device__ __forceinline__ void mma16816(float* c, const uint32_t* a, uint32_t b0, uint32_t b1) {
    asm volatile("mma.sync.aligned.m16n8k16.row.col.f32.bf16.bf16.f32 "
                 "{%0,%1,%2,%3}, {%4,%5,%6,%7}, {%8,%9}, {%0,%1,%2,%3};"
                 : "+f"(c[0]), "+f"(c[1]), "+f"(c[2]), "+f"(c[3])
                 : "r"(a[0]), "r"(a[1]), "r"(a[2]), "r"(a[3]), "r"(b0), "r"(b1));
}

// ---------------- CSR build ----------------
__global__ void zero2_kernel(int* a, int* b, int n) {
    int i = blockIdx.x * blockDim.x + threadIdx.x;
    if (i < n) { a[i] = 0; b[i] = 0; }
}
__global__ void count_kernel(const int* __restrict__ ei, int* __restrict__ deg,
                             int* __restrict__ cnt) {
    int idx = blockIdx.x * blockDim.x + threadIdx.x;
    if (idx >= RR * EE) return;
    int r = idx / EE;
    int e = idx - r * EE;
    int src = ei[(size_t)r * 2 * EE + e];
    int dst = ei[(size_t)r * 2 * EE + EE + e];
    atomicAdd(&deg[r * NN + src], 1);
    atomicAdd(&cnt[r * NN + dst], 1);
}
__global__ void dinv_kernel(const int* __restrict__ deg, float* __restrict__ dinv) {
    int i = blockIdx.x * blockDim.x + threadIdx.x;
    if (i >= RR * NN) return;
    int d = deg[i];
    dinv[i] = (d > 0) ? rsqrtf((float)d) : 0.0f;
}
__global__ void scan1_kernel(const int* __restrict__ in, int* __restrict__ out,
                             int* __restrict__ bsums, int n) {
    __shared__ int sh[1024];
    int i = blockIdx.x * 1024 + threadIdx.x;
    int v = (i < n) ? in[i] : 0;
    sh[threadIdx.x] = v;
    __syncthreads();
    for (int off = 1; off < 1024; off <<= 1) {
        int t = (threadIdx.x >= off) ? sh[threadIdx.x - off] : 0;
        __syncthreads();
        sh[threadIdx.x] += t;
        __syncthreads();
    }
    if (i < n) out[i] = sh[threadIdx.x] - v;
    if (threadIdx.x == 1023) bsums[blockIdx.x] = sh[1023];
}
__global__ void scan2_kernel(int* bsums, int nb) {
    __shared__ int sh[512];
    int v = (threadIdx.x < nb) ? bsums[threadIdx.x] : 0;
    sh[threadIdx.x] = v;
    __syncthreads();
    for (int off = 1; off < 512; off <<= 1) {
        int t = (threadIdx.x >= off) ? sh[threadIdx.x - off] : 0;
        __syncthreads();
        sh[threadIdx.x] += t;
        __syncthreads();
    }
    if (threadIdx.x < nb) bsums[threadIdx.x] = sh[threadIdx.x] - v;
}
__global__ void scan3_kernel(int* __restrict__ rp, const int* __restrict__ bsums,
                             int* __restrict__ cur, int n, int total) {
    int i = blockIdx.x * 1024 + threadIdx.x;
    if (i < n) {
        int v = rp[i] + bsums[blockIdx.x];
        rp[i] = v;
        cur[i] = v;
    }
    if (i == 0) rp[n] = total;
}
__global__ void fill_kernel(const int* __restrict__ ei, int* __restrict__ cur,
                            int* __restrict__ col) {
    int idx = blockIdx.x * blockDim.x + threadIdx.x;
    if (idx >= RR * EE) return;
    int r = idx / EE;
    int e = idx - r * EE;
    int src = ei[(size_t)r * 2 * EE + e];
    int dst = ei[(size_t)r * 2 * EE + EE + e];
    int pos = atomicAdd(&cur[r * NN + dst], 1);
    col[pos] = src;
}

// ---------------- weight preconversion: transpose + bf16 split + SW128 image ----------------
// chunk layout: [0,108): cheb GEMM g=c/6, kloc=(c%6)*64 into [384,128]
//               [108,120): proj, kloc=(c-108)*64 into [768,128]
//               [120,122): cls1, kloc=(c-120)*64 into [128,128]
__global__ void preconv_kernel(const float* __restrict__ chebW,
                               const float* __restrict__ projW,
                               const float* __restrict__ W1,
                               __nv_bfloat16* __restrict__ Bhi,
                               __nv_bfloat16* __restrict__ Blo) {
    int idx = blockIdx.x * blockDim.x + threadIdx.x;
    if (idx >= NCH_TOTAL * 8192) return;
    int c = idx >> 13;
    int e = idx & 8191;
    int n = e >> 6;
    int kk = e & 63;
    const float* src;
    int kloc;
    if (c < 108)      { src = chebW + (size_t)(c / 6) * (KK * HH * HH); kloc = (c % 6) * 64; }
    else if (c < 120) { src = projW; kloc = (c - 108) * 64; }
    else              { src = W1;    kloc = (c - 120) * 64; }
    float v = src[(size_t)(kloc + kk) * HH + n];           // B[n][k] = W[k][n]
    __nv_bfloat16 hi = __float2bfloat16(v);
    __nv_bfloat16 lo = __float2bfloat16(v - __bfloat162float(hi));
    uint32_t off = SW128((uint32_t)(n * 128 + kk * 2)) >> 1;
    Bhi[(size_t)c * 8192 + off] = hi;
    Blo[(size_t)c * 8192 + off] = lo;
}

// ---------------- HMMA bf16 split GEMM ----------------
// C[N,128] = act( sum_K A @ B ), fp32 A split to bf16 hi/lo (3 products).
// K in chunks of 64. smem (64KB): Ahi 0 | Alo 16K | Bhi 32K | Blo 48K.
struct Seg { const float* p[6]; };

__global__ __launch_bounds__(256, 2)
void gemm_mma(Seg A, const __nv_bfloat16* __restrict__ Bhi,
              const __nv_bfloat16* __restrict__ Blo,
              const float* __restrict__ bias, float* __restrict__ C,
              int nchunks, int relu) {
    extern __shared__ char smem[];
    const uint32_t sb = smem_u32(smem);
    const int tid = threadIdx.x;
    const int wid = tid >> 5;
    const int lane = tid & 31;
    const int bm = blockIdx.x * 128;
    const int mwarp = (wid >> 2) * 64;     // 2 m-groups
    const int nwarp = (wid & 3) * 32;      // 4 n-groups

    // ldmatrix per-thread address components (same formula for A and B tiles)
    const int sel = lane >> 3;                 // 0..3
    const int r8 = lane & 7;
    const int lm_roff = (sel & 1) * 8 + r8;    // row within 16
    const int lm_kbyte = (sel >> 1) * 16;      // 0 or 16 bytes (8 elems)

    float c[4][4][4];
#pragma unroll
    for (int i = 0; i < 4; i++)
#pragma unroll
        for (int j = 0; j < 4; j++)
#pragma unroll
            for (int q = 0; q < 4; q++) c[i][j][q] = 0.f;

    for (int ch = 0; ch < nchunks; ch++) {
        // ---- stage chunk into smem ----
        const float* Ap = A.p[ch >> 1];
        const int kc = (ch & 1) * 64;
        // A: 128 rows x 64 cols fp32 -> bf16 hi/lo, SW128
#pragma unroll
        for (int it = 0; it < 8; it++) {
            int q = it * 256 + tid;            // 0..2047
            int m = q >> 4;
            int kk = (q & 15) * 4;
            int gm = bm + m;
            float4 v = make_float4(0.f, 0.f, 0.f, 0.f);
            if (gm < NN) v = *(const float4*)(Ap + (size_t)gm * HH + kc + kk);
            uint32_t off = SW128((uint32_t)(m * 128 + kk * 2));
            __nv_bfloat162 h0, h1, l0, l1;
            h0.x = __float2bfloat16(v.x);
            h0.y = __float2bfloat16(v.y);
            h1.x = __float2bfloat16(v.z);
            h1.y = __float2bfloat16(v.w);
            l0.x = __float2bfloat16(v.x - __bfloat162float(h0.x));
            l0.y = __float2bfloat16(v.y - __bfloat162float(h0.y));
            l1.x = __float2bfloat16(v.z - __bfloat162float(h1.x));
            l1.y = __float2bfloat16(v.w - __bfloat162float(h1.y));
            uint2 hw, lw;
            hw.x = *(uint32_t*)&h0; hw.y = *(uint32_t*)&h1;
            lw.x = *(uint32_t*)&l0; lw.y = *(uint32_t*)&l1;
            *(uint2*)(smem + off) = hw;
            *(uint2*)(smem + 16384 + off) = lw;
        }
        // B: linear copy of pre-swizzled images
        {
            const int4* shp = (const int4*)(Bhi + (size_t)ch * 8192);
            const int4* slp = (const int4*)(Blo + (size_t)ch * 8192);
            int4* dh = (int4*)(smem + 32768);
            int4* dl = (int4*)(smem + 49152);
#pragma unroll
            for (int it = 0; it < 4; it++) {
                int q = it * 256 + tid;        // 0..1023
                dh[q] = shp[q];
                dl[q] = slp[q];
            }
        }
        __syncthreads();

        // ---- MMA: 4 k-steps of 16 ----
#pragma unroll
        for (int ks = 0; ks < 4; ks++) {
            const int kb = ks * 32 + lm_kbyte;   // k byte offset
            uint32_t afr[16], bfr[8];
            // B-low fragments (2x ldmatrix.x4 over n16 each)
#pragma unroll
            for (int g = 0; g < 2; g++)
                ldsm4(bfr + g * 4,
                      sb + 49152 + SW128((uint32_t)((nwarp + g * 16 + lm_roff) * 128 + kb)));
            // A-high fragments (4 m16 tiles)
#pragma unroll
            for (int mt = 0; mt < 4; mt++)
                ldsm4(afr + mt * 4,
                      sb + SW128((uint32_t)((mwarp + mt * 16 + lm_roff) * 128 + kb)));
            // P1 = Ahi * Blo
#pragma unroll
            for (int mt = 0; mt < 4; mt++)
#pragma unroll
                for (int nt = 0; nt < 4; nt++)
                    mma16816(c[mt][nt], afr + mt * 4,
                             bfr[(nt >> 1) * 4 + (nt & 1)], bfr[(nt >> 1) * 4 + 2 + (nt & 1)]);
            // B-high fragments (reuse bfr)
#pragma unroll
            for (int g = 0; g < 2; g++)
                ldsm4(bfr + g * 4,
                      sb + 32768 + SW128((uint32_t)((nwarp + g * 16 + lm_roff) * 128 + kb)));
            // P2 = Ahi * Bhi
#pragma unroll
            for (int mt = 0; mt < 4; mt++)
#pragma unroll
                for (int nt = 0; nt < 4; nt++)
                    mma16816(c[mt][nt], afr + mt * 4,
                             bfr[(nt >> 1) * 4 + (nt & 1)], bfr[(nt >> 1) * 4 + 2 + (nt & 1)]);
            // A-low fragments (reuse afr)
#pragma unroll
            for (int mt = 0; mt < 4; mt++)
                ldsm4(afr + mt * 4,
                      sb + 16384 + SW128((uint32_t)((mwarp + mt * 16 + lm_roff) * 128 + kb)));
            // P3 = Alo * Bhi
#pragma unroll
            for (int mt = 0; mt < 4; mt++)
#pragma unroll
                for (int nt = 0; nt < 4; nt++)
                    mma16816(c[mt][nt], afr + mt * 4,
                             bfr[(nt >> 1) * 4 + (nt & 1)], bfr[(nt >> 1) * 4 + 2 + (nt & 1)]);
        }
        __syncthreads();
    }

    // ---- epilogue: bias + relu + store ----
    const int crow = lane >> 2;
    const int ccol = (lane & 3) * 2;
#pragma unroll
    for (int mt = 0; mt < 4; mt++) {
#pragma unroll
        for (int half = 0; half < 2; half++) {
            int gm = bm + mwarp + mt * 16 + crow + half * 8;
            if (gm < NN) {
                float* cp = C + (size_t)gm * HH;
#pragma unroll
                for (int nt = 0; nt < 4; nt++) {
                    int gn = nwarp + nt * 8 + ccol;
                    float v0 = c[mt][nt][half * 2 + 0] + bias[gn];
                    float v1 = c[mt][nt][half * 2 + 1] + bias[gn + 1];
                    if (relu) { v0 = fmaxf(v0, 0.f); v1 = fmaxf(v1, 0.f); }
                    float2 o; o.x = v0; o.y = v1;
                    *(float2*)(cp + gn) = o;
                }
            }
        }
    }
}

// ---------------- sparse propagation ----------------
__global__ void prop_kernel(const float4* __restrict__ hin, float4* __restrict__ hout,
                            const int* __restrict__ rowptr, const int* __restrict__ col,
                            const float* __restrict__ dinv, const float4* __restrict__ sub,
                            float alpha) {
    int t = blockIdx.x * blockDim.x + threadIdx.x;
    int w = t >> 5;
    int lane = t & 31;
    if (w >= NN) return;
    int e = rowptr[w];
    int e1 = rowptr[w + 1];
    float4 acc = make_float4(0.f, 0.f, 0.f, 0.f);
    for (; e + 1 < e1; e += 2) {
        int sa = __ldg(&col[e]);
        int sb = __ldg(&col[e + 1]);
        float wa = __ldg(&dinv[sa]);
        float wb = __ldg(&dinv[sb]);
        float4 va = hin[(size_t)sa * 32 + lane];
        float4 vb = hin[(size_t)sb * 32 + lane];
        acc.x += wa * va.x + wb * vb.x;
        acc.y += wa * va.y + wb * vb.y;
        acc.z += wa * va.z + wb * vb.z;
        acc.w += wa * va.w + wb * vb.w;
    }
    if (e < e1) {
        int sa = __ldg(&col[e]);
        float wa = __ldg(&dinv[sa]);
        float4 va = hin[(size_t)sa * 32 + lane];
        acc.x += wa * va.x;
        acc.y += wa * va.y;
        acc.z += wa * va.z;
        acc.w += wa * va.w;
    }
    float sc = -alpha * dinv[w];
    float4 r;
    r.x = sc * acc.x; r.y = sc * acc.y; r.z = sc * acc.z; r.w = sc * acc.w;
    if (sub) {
        float4 u = sub[(size_t)w * 32 + lane];
        r.x -= u.x; r.y -= u.y; r.z -= u.z; r.w -= u.w;
    }
    hout[(size_t)w * 32 + lane] = r;
}

// ---------------- final: logit + aux ----------------
__global__ void final_kernel(const float4* __restrict__ hc, const float4* __restrict__ emb,
                             const float* __restrict__ clsW2, const float* __restrict__ clsb2,
                             const float* __restrict__ auxW, const float* __restrict__ auxB,
                             float* __restrict__ out) {
    int t = blockIdx.x * blockDim.x + threadIdx.x;
    int gw = t >> 5;
    int lane = t & 31;
    if (gw >= (RR + 1) * NN) return;
    const float4* vec;
    const float4* wv;
    float b;
    if (gw < NN) {
        vec = hc + (size_t)gw * 32;
        wv = (const float4*)clsW2;
        b = clsb2[0];
    } else {
        int r = (gw - NN) / NN;
        int n = (gw - NN) - r * NN;
        vec = emb + ((size_t)r * NN + n) * 32;
        wv = (const float4*)(auxW + r * HH);
        b = auxB[r];
    }
    float4 a = vec[lane];
    float4 w = wv[lane];
    float s = a.x * w.x + a.y * w.y + a.z * w.z + a.w * w.w;
#pragma unroll
    for (int off = 16; off; off >>= 1) s += __shfl_xor_sync(0xFFFFFFFFu, s, off);
    if (lane == 0) out[gw] = s + b;
}

// ---------------- launch ----------------
extern "C" void kernel_launch(void* const* d_in, const int* in_sizes, int n_in,
                              void* d_out, int out_size) {
    (void)in_sizes; (void)n_in; (void)out_size;
    const float* x     = (const float*)d_in[0];
    const int*   ei    = (const int*)d_in[1];
    const float* chebW = (const float*)d_in[2];
    const float* chebB = (const float*)d_in[3];
    const float* projW = (const float*)d_in[4];
    const float* projB = (const float*)d_in[5];
    const float* W1    = (const float*)d_in[6];
    const float* b1    = (const float*)d_in[7];
    const float* W2    = (const float*)d_in[8];
    const float* b2    = (const float*)d_in[9];
    const float* auxW  = (const float*)d_in[10];
    const float* auxB  = (const float*)d_in[11];
    float* out = (float*)d_out;

    float *emb, *hA, *hB, *tx, *tx2, *dinv;
    int *deg, *cnt, *rp, *cur, *col, *bs;
    __nv_bfloat16 *Bhi, *Blo;
    cudaGetSymbolAddress((void**)&emb, g_emb);
    cudaGetSymbolAddress((void**)&hA, g_hA);
    cudaGetSymbolAddress((void**)&hB, g_hB);
    cudaGetSymbolAddress((void**)&tx, g_tx);
    cudaGetSymbolAddress((void**)&tx2, g_tx2);
    cudaGetSymbolAddress((void**)&dinv, g_dinv);
    cudaGetSymbolAddress((void**)&deg, g_deg);
    cudaGetSymbolAddress((void**)&cnt, g_cnt);
    cudaGetSymbolAddress((void**)&rp, g_rp);
    cudaGetSymbolAddress((void**)&cur, g_cur);
    cudaGetSymbolAddress((void**)&col, g_col);
    cudaGetSymbolAddress((void**)&bs, g_bsums);
    cudaGetSymbolAddress((void**)&Bhi, g_Bhi);
    cudaGetSymbolAddress((void**)&Blo, g_Blo);

    const int SMEM_BYTES = 65536;
    cudaFuncSetAttribute(gemm_mma, cudaFuncAttributeMaxDynamicSharedMemorySize, SMEM_BYTES);

    // CSR build
    zero2_kernel<<<(RR * NN + 255) / 256, 256>>>(deg, cnt, RR * NN);
    count_kernel<<<(RR * EE + 255) / 256, 256>>>(ei, deg, cnt);
    dinv_kernel<<<(RR * NN + 255) / 256, 256>>>(deg, dinv);
    const int ntot = RR * NN;
    const int nb = (ntot + 1023) / 1024;
    scan1_kernel<<<nb, 1024>>>(cnt, rp, bs, ntot);
    scan2_kernel<<<1, 512>>>(bs, nb);
    scan3_kernel<<<nb, 1024>>>(rp, bs, cur, ntot, RR * EE);
    fill_kernel<<<(RR * EE + 255) / 256, 256>>>(ei, cur, col);

    // weight preconversion
    preconv_kernel<<<(NCH_TOTAL * 8192 + 255) / 256, 256>>>(chebW, projW, W1, Bhi, Blo);

    const int propBlocks = (NN * 32 + 255) / 256;
    const int gemmGrid = (NN + 127) / 128;   // 391

    for (int r = 0; r < RR; r++) {
        const float* h = x;
        for (int l = 0; l < LL; l++) {
            prop_kernel<<<propBlocks, 256>>>((const float4*)h, (float4*)tx,
                                             rp + r * NN, col, dinv + r * NN, nullptr, 1.0f);
            prop_kernel<<<propBlocks, 256>>>((const float4*)tx, (float4*)tx2,
                                             rp + r * NN, col, dinv + r * NN,
                                             (const float4*)h, 2.0f);
            float* o = (l == LL - 1) ? (emb + (size_t)r * NN * HH) : (l == 0 ? hA : hB);
            Seg s;
            s.p[0] = h; s.p[1] = tx; s.p[2] = tx2;
            s.p[3] = nullptr; s.p[4] = nullptr; s.p[5] = nullptr;
            int g = r * LL + l;
            gemm_mma<<<gemmGrid, 256, SMEM_BYTES>>>(s, Bhi + (size_t)(g * 6) * 8192,
                                                    Blo + (size_t)(g * 6) * 8192,
                                                    chebB + (size_t)g * HH, o, 6, 1);
            h = o;
        }
    }

    // hp = relu(concat_r(emb) @ projW + projB)  (12 chunks, 6 segments)
    Seg sp;
    for (int r = 0; r < RR; r++) sp.p[r] = emb + (size_t)r * NN * HH;
    gemm_mma<<<gemmGrid, 256, SMEM_BYTES>>>(sp, Bhi + (size_t)108 * 8192,
                                            Blo + (size_t)108 * 8192, projB, hA, 12, 1);

    // hc = relu(hp @ W1 + b1)  (2 chunks)
    Seg s1;
    s1.p[0] = hA;
    for (int i = 1; i < 6; i++) s1.p[i] = nullptr;
    gemm_mma<<<gemmGrid, 256, SMEM_BYTES>>>(s1, Bhi + (size_t)120 * 8192,
                                            Blo + (size_t)120 * 8192, b1, hB, 2, 1);

    final_kernel<<<((RR + 1) * NN * 32 + 255) / 256, 256>>>(
        (const float4*)hB, (const float4*)emb, W2, b2, auxW, auxB, out);
}

// round 4
// speedup vs baseline: 1.5834x; 1.1239x over previous
#include <cuda_runtime.h>
#include <cuda_bf16.h>
#include <cstdint>

#define NN 50000
#define HH 128
#define RR 6
#define EE 800000
#define LL 3
#define KK 3

#define NT 391                     // row tiles of 128
#define NPAD (NT * 128)            // 50048
#define IMG_ELEMS ((size_t)NT * 2 * 8192)   // bf16 elems per split image (hi or lo)

// total B chunks: 18 cheb GEMMs * 6 + proj 12 + cls1 2 = 122
#define NCH_TOTAL 122

// ---------------- static device scratch ----------------
__device__ __align__(16) static float g_emb[(size_t)RR * NN * HH];
__device__ __align__(16) static float g_hA[(size_t)NN * HH];
__device__ __align__(16) static float g_hB[(size_t)NN * HH];
__device__ __align__(16) static float g_tx[(size_t)NN * HH];
__device__ __align__(16) static float g_tx2[(size_t)NN * HH];
__device__ static int   g_deg[RR * NN];
__device__ static int   g_cnt[RR * NN];
__device__ static int   g_rp[RR * NN + 1];
__device__ static int   g_cur[RR * NN];
__device__ static int   g_col[RR * EE];
__device__ static float g_dinv[RR * NN];
__device__ static int   g_bsums[1024];
// pre-swizzled bf16 weight tile images: [chunk][8192] (16KB each)
__device__ __align__(16) static __nv_bfloat16 g_Bhi[(size_t)NCH_TOTAL * 8192];
__device__ __align__(16) static __nv_bfloat16 g_Blo[(size_t)NCH_TOTAL * 8192];
// split activation images (pre-swizzled SMEM tile images): [tile][parity][8192]
__device__ __align__(16) static __nv_bfloat16 g_xs_hi[IMG_ELEMS],  g_xs_lo[IMG_ELEMS];
__device__ __align__(16) static __nv_bfloat16 g_tx_hi[IMG_ELEMS],  g_tx_lo[IMG_ELEMS];
__device__ __align__(16) static __nv_bfloat16 g_tx2_hi[IMG_ELEMS], g_tx2_lo[IMG_ELEMS];
__device__ __align__(16) static __nv_bfloat16 g_hA_hi[IMG_ELEMS],  g_hA_lo[IMG_ELEMS];
__device__ __align__(16) static __nv_bfloat16 g_hB_hi[IMG_ELEMS],  g_hB_lo[IMG_ELEMS];
__device__ __align__(16) static __nv_bfloat16 g_es_hi[(size_t)RR * IMG_ELEMS];
__device__ __align__(16) static __nv_bfloat16 g_es_lo[(size_t)RR * IMG_ELEMS];

#define SW128(off) ((off) ^ (((off) >> 3) & 0x70))

__device__ __forceinline__ uint32_t smem_u32(const void* p) {
    uint32_t a;
    asm("{ .reg .u64 t; cvta.to.shared.u64 t, %1; cvt.u32.u64 %0, t; }" : "=r"(a) : "l"(p));
    return a;
}
__device__ __forceinline__ void ldsm4(uint32_t* r, uint32_t addr) {
    asm volatile("ldmatrix.sync.aligned.m8n8.x4.shared.b16 {%0,%1,%2,%3}, [%4];"
                 : "=r"(r[0]), "=r"(r[1]), "=r"(r[2]), "=r"(r[3]) : "r"(addr));
}
__device__ __forceinline__ void mma16816(float* c, const uint32_t* a, uint32_t b0, uint32_t b1) {
    asm volatile("mma.sync.aligned.m16n8k16.row.col.f32.bf16.bf16.f32 "
                 "{%0,%1,%2,%3}, {%4,%5,%6,%7}, {%8,%9}, {%0,%1,%2,%3};"
                 : "+f"(c[0]), "+f"(c[1]), "+f"(c[2]), "+f"(c[3])
                 : "r"(a[0]), "r"(a[1]), "r"(a[2]), "r"(a[3]), "r"(b0), "r"(b1));
}
__device__ __forceinline__ void cpa16(uint32_t s, const void* g) {
    asm volatile("cp.async.cg.shared.global [%0], [%1], 16;" :: "r"(s), "l"(g));
}

// split 4 floats (cols kk..kk+3 of row mloc, chunk image idx) and store 8B to hi/lo images
__device__ __forceinline__ void split_store4(__nv_bfloat16* hi, __nv_bfloat16* lo,
                                             size_t imgByte, int mloc, int kk,
                                             float vx, float vy, float vz, float vw) {
    __nv_bfloat162 h0, h1, l0, l1;
    h0.x = __float2bfloat16(vx); h0.y = __float2bfloat16(vy);
    h1.x = __float2bfloat16(vz); h1.y = __float2bfloat16(vw);
    l0.x = __float2bfloat16(vx - __bfloat162float(h0.x));
    l0.y = __float2bfloat16(vy - __bfloat162float(h0.y));
    l1.x = __float2bfloat16(vz - __bfloat162float(h1.x));
    l1.y = __float2bfloat16(vw - __bfloat162float(h1.y));
    uint32_t off = SW128((uint32_t)(mloc * 128 + kk * 2));
    uint2 hv, lv;
    hv.x = *(uint32_t*)&h0; hv.y = *(uint32_t*)&h1;
    lv.x = *(uint32_t*)&l0; lv.y = *(uint32_t*)&l1;
    *(uint2*)((char*)hi + imgByte + off) = hv;
    *(uint2*)((char*)lo + imgByte + off) = lv;
}

// ---------------- CSR build ----------------
__global__ void zero2_kernel(int* a, int* b, int n) {
    int i = blockIdx.x * blockDim.x + threadIdx.x;
    if (i < n) { a[i] = 0; b[i] = 0; }
}
__global__ void count_kernel(const int* __restrict__ ei, int* __restrict__ deg,
                             int* __restrict__ cnt) {
    int idx = blockIdx.x * blockDim.x + threadIdx.x;
    if (idx >= RR * EE) return;
    int r = idx / EE;
    int e = idx - r * EE;
    int src = ei[(size_t)r * 2 * EE + e];
    int dst = ei[(size_t)r * 2 * EE + EE + e];
    atomicAdd(&deg[r * NN + src], 1);
    atomicAdd(&cnt[r * NN + dst], 1);
}
__global__ void dinv_kernel(const int* __restrict__ deg, float* __restrict__ dinv) {
    int i = blockIdx.x * blockDim.x + threadIdx.x;
    if (i >= RR * NN) return;
    int d = deg[i];
    dinv[i] = (d > 0) ? rsqrtf((float)d) : 0.0f;
}
__global__ void scan1_kernel(const int* __restrict__ in, int* __restrict__ out,
                             int* __restrict__ bsums, int n) {
    __shared__ int sh[1024];
    int i = blockIdx.x * 1024 + threadIdx.x;
    int v = (i < n) ? in[i] : 0;
    sh[threadIdx.x] = v;
    __syncthreads();
    for (int off = 1; off < 1024; off <<= 1) {
        int t = (threadIdx.x >= off) ? sh[threadIdx.x - off] : 0;
        __syncthreads();
        sh[threadIdx.x] += t;
        __syncthreads();
    }
    if (i < n) out[i] = sh[threadIdx.x] - v;
    if (threadIdx.x == 1023) bsums[blockIdx.x] = sh[1023];
}
__global__ void scan2_kernel(int* bsums, int nb) {
    __shared__ int sh[512];
    int v = (threadIdx.x < nb) ? bsums[threadIdx.x] : 0;
    sh[threadIdx.x] = v;
    __syncthreads();
    for (int off = 1; off < 512; off <<= 1) {
        int t = (threadIdx.x >= off) ? sh[threadIdx.x - off] : 0;
        __syncthreads();
        sh[threadIdx.x] += t;
        __syncthreads();
    }
    if (threadIdx.x < nb) bsums[threadIdx.x] = sh[threadIdx.x] - v;
}
__global__ void scan3_kernel(int* __restrict__ rp, const int* __restrict__ bsums,
                             int* __restrict__ cur, int n, int total) {
    int i = blockIdx.x * 1024 + threadIdx.x;
    if (i < n) {
        int v = rp[i] + bsums[blockIdx.x];
        rp[i] = v;
        cur[i] = v;
    }
    if (i == 0) rp[n] = total;
}
__global__ void fill_kernel(const int* __restrict__ ei, int* __restrict__ cur,
                            int* __restrict__ col) {
    int idx = blockIdx.x * blockDim.x + threadIdx.x;
    if (idx >= RR * EE) return;
    int r = idx / EE;
    int e = idx - r * EE;
    int src = ei[(size_t)r * 2 * EE + e];
    int dst = ei[(size_t)r * 2 * EE + EE + e];
    int pos = atomicAdd(&cur[r * NN + dst], 1);
    col[pos] = src;
}

// ---------------- weight preconversion ----------------
__global__ void preconv_kernel(const float* __restrict__ chebW,
                               const float* __restrict__ projW,
                               const float* __restrict__ W1,
                               __nv_bfloat16* __restrict__ Bhi,
                               __nv_bfloat16* __restrict__ Blo) {
    int idx = blockIdx.x * blockDim.x + threadIdx.x;
    if (idx >= NCH_TOTAL * 8192) return;
    int c = idx >> 13;
    int e = idx & 8191;
    int n = e >> 6;
    int kk = e & 63;
    const float* src;
    int kloc;
    if (c < 108)      { src = chebW + (size_t)(c / 6) * (KK * HH * HH); kloc = (c % 6) * 64; }
    else if (c < 120) { src = projW; kloc = (c - 108) * 64; }
    else              { src = W1;    kloc = (c - 120) * 64; }
    float v = src[(size_t)(kloc + kk) * HH + n];           // B[n][k] = W[k][n]
    __nv_bfloat16 hi = __float2bfloat16(v);
    __nv_bfloat16 lo = __float2bfloat16(v - __bfloat162float(hi));
    uint32_t off = SW128((uint32_t)(n * 128 + kk * 2)) >> 1;
    Bhi[(size_t)c * 8192 + off] = hi;
    Blo[(size_t)c * 8192 + off] = lo;
}

// ---------------- x -> split images (once) ----------------
__global__ void xsplit_kernel(const float4* __restrict__ x,
                              __nv_bfloat16* __restrict__ hi, __nv_bfloat16* __restrict__ lo) {
    int t = blockIdx.x * blockDim.x + threadIdx.x;
    if (t >= NN * 32) return;
    int row = t >> 5;
    int lane = t & 31;
    float4 v = x[t];
    int tile = row >> 7;
    int mloc = row & 127;
    int p = lane >> 4;
    int kk = (lane * 4) & 63;
    size_t imgB = (size_t)(tile * 2 + p) * 16384;
    split_store4(hi, lo, imgB, mloc, kk, v.x, v.y, v.z, v.w);
}

// ---------------- HMMA bf16 split GEMM ----------------
// A segments are pre-split, pre-swizzled tile images. Staging = linear cp.async.
struct Seg { const __nv_bfloat16* hi[6]; const __nv_bfloat16* lo[6]; };

__global__ __launch_bounds__(256, 2)
void gemm_mma(Seg A, const __nv_bfloat16* __restrict__ Bhi,
              const __nv_bfloat16* __restrict__ Blo,
              const float* __restrict__ bias, float* __restrict__ C,
              __nv_bfloat16* __restrict__ Ohi, __nv_bfloat16* __restrict__ Olo,
              int nchunks, int relu) {
    extern __shared__ char smem[];
    const uint32_t sb = smem_u32(smem);
    const int tid = threadIdx.x;
    const int wid = tid >> 5;
    const int lane = tid & 31;
    const int bm = blockIdx.x * 128;
    const int mwarp = (wid >> 2) * 64;     // 2 m-groups
    const int nwarp = (wid & 3) * 32;      // 4 n-groups

    const int sel = lane >> 3;
    const int r8 = lane & 7;
    const int lm_roff = (sel & 1) * 8 + r8;
    const int lm_kbyte = (sel >> 1) * 16;

    float c[4][4][4];
#pragma unroll
    for (int i = 0; i < 4; i++)
#pragma unroll
        for (int j = 0; j < 4; j++)
#pragma unroll
            for (int q = 0; q < 4; q++) c[i][j][q] = 0.f;

    for (int ch = 0; ch < nchunks; ch++) {
        // ---- stage: 4 linear 16KB cp.async copies ----
        const int seg = ch >> 1, par = ch & 1;
        const char* pAh = (const char*)A.hi[seg] + (size_t)(blockIdx.x * 2 + par) * 16384;
        const char* pAl = (const char*)A.lo[seg] + (size_t)(blockIdx.x * 2 + par) * 16384;
        const char* pBh = (const char*)(Bhi + (size_t)ch * 8192);
        const char* pBl = (const char*)(Blo + (size_t)ch * 8192);
#pragma unroll
        for (int it = 0; it < 4; it++) {
            uint32_t q = (uint32_t)(it * 256 + tid) * 16;   // 0..16368
            cpa16(sb + q,         pAh + q);
            cpa16(sb + 16384 + q, pAl + q);
            cpa16(sb + 32768 + q, pBh + q);
            cpa16(sb + 49152 + q, pBl + q);
        }
        asm volatile("cp.async.commit_group;");
        asm volatile("cp.async.wait_group 0;");
        __syncthreads();

        // ---- MMA: 4 k-steps of 16 ----
#pragma unroll
        for (int ks = 0; ks < 4; ks++) {
            const int kb = ks * 32 + lm_kbyte;
            uint32_t afr[16], bfr[8];
#pragma unroll
            for (int g = 0; g < 2; g++)
                ldsm4(bfr + g * 4,
                      sb + 49152 + SW128((uint32_t)((nwarp + g * 16 + lm_roff) * 128 + kb)));
#pragma unroll
            for (int mt = 0; mt < 4; mt++)
                ldsm4(afr + mt * 4,
                      sb + SW128((uint32_t)((mwarp + mt * 16 + lm_roff) * 128 + kb)));
            // Ahi * Blo
#pragma unroll
            for (int mt = 0; mt < 4; mt++)
#pragma unroll
                for (int nt = 0; nt < 4; nt++)
                    mma16816(c[mt][nt], afr + mt * 4,
                             bfr[(nt >> 1) * 4 + (nt & 1)], bfr[(nt >> 1) * 4 + 2 + (nt & 1)]);
#pragma unroll
            for (int g = 0; g < 2; g++)
                ldsm4(bfr + g * 4,
                      sb + 32768 + SW128((uint32_t)((nwarp + g * 16 + lm_roff) * 128 + kb)));
            // Ahi * Bhi
#pragma unroll
            for (int mt = 0; mt < 4; mt++)
#pragma unroll
                for (int nt = 0; nt < 4; nt++)
                    mma16816(c[mt][nt], afr + mt * 4,
                             bfr[(nt >> 1) * 4 + (nt & 1)], bfr[(nt >> 1) * 4 + 2 + (nt & 1)]);
#pragma unroll
            for (int mt = 0; mt < 4; mt++)
                ldsm4(afr + mt * 4,
                      sb + 16384 + SW128((uint32_t)((mwarp + mt * 16 + lm_roff) * 128 + kb)));
            // Alo * Bhi
#pragma unroll
            for (int mt = 0; mt < 4; mt++)
#pragma unroll
                for (int nt = 0; nt < 4; nt++)
                    mma16816(c[mt][nt], afr + mt * 4,
                             bfr[(nt >> 1) * 4 + (nt & 1)], bfr[(nt >> 1) * 4 + 2 + (nt & 1)]);
        }
        __syncthreads();
    }

    // ---- epilogue: bias + relu + fp32 store + optional split-image store ----
    const int crow = lane >> 2;
    const int ccol = (lane & 3) * 2;
#pragma unroll
    for (int mt = 0; mt < 4; mt++) {
#pragma unroll
        for (int half = 0; half < 2; half++) {
            int mloc = mwarp + mt * 16 + crow + half * 8;
            int gm = bm + mloc;
            if (gm < NN) {
                float* cp = C + (size_t)gm * HH;
#pragma unroll
                for (int nt = 0; nt < 4; nt++) {
                    int gn = nwarp + nt * 8 + ccol;
                    float v0 = c[mt][nt][half * 2 + 0] + bias[gn];
                    float v1 = c[mt][nt][half * 2 + 1] + bias[gn + 1];
                    if (relu) { v0 = fmaxf(v0, 0.f); v1 = fmaxf(v1, 0.f); }
                    float2 o; o.x = v0; o.y = v1;
                    *(float2*)(cp + gn) = o;
                    if (Ohi) {
                        __nv_bfloat162 h2, l2;
                        h2.x = __float2bfloat16(v0);
                        h2.y = __float2bfloat16(v1);
                        l2.x = __float2bfloat16(v0 - __bfloat162float(h2.x));
                        l2.y = __float2bfloat16(v1 - __bfloat162float(h2.y));
                        int p = gn >> 6;
                        int kk = gn & 63;
                        size_t imgB = (size_t)(blockIdx.x * 2 + p) * 16384;
                        uint32_t off = SW128((uint32_t)(mloc * 128 + kk * 2));
                        *(uint32_t*)((char*)Ohi + imgB + off) = *(uint32_t*)&h2;
                        *(uint32_t*)((char*)Olo + imgB + off) = *(uint32_t*)&l2;
                    }
                }
            }
        }
    }
}

// ---------------- sparse propagation (+ split-image output) ----------------
__global__ void prop_kernel(const float4* __restrict__ hin, float4* __restrict__ hout,
                            const int* __restrict__ rowptr, const int* __restrict__ col,
                            const float* __restrict__ dinv, const float4* __restrict__ sub,
                            float alpha,
                            __nv_bfloat16* __restrict__ Ohi, __nv_bfloat16* __restrict__ Olo) {
    int t = blockIdx.x * blockDim.x + threadIdx.x;
    int w = t >> 5;
    int lane = t & 31;
    if (w >= NN) return;
    int e = rowptr[w];
    int e1 = rowptr[w + 1];
    float4 acc = make_float4(0.f, 0.f, 0.f, 0.f);
    for (; e + 1 < e1; e += 2) {
        int sa = __ldg(&col[e]);
        int sbi = __ldg(&col[e + 1]);
        float wa = __ldg(&dinv[sa]);
        float wb = __ldg(&dinv[sbi]);
        float4 va = hin[(size_t)sa * 32 + lane];
        float4 vb = hin[(size_t)sbi * 32 + lane];
        acc.x += wa * va.x + wb * vb.x;
        acc.y += wa * va.y + wb * vb.y;
        acc.z += wa * va.z + wb * vb.z;
        acc.w += wa * va.w + wb * vb.w;
    }
    if (e < e1) {
        int sa = __ldg(&col[e]);
        float wa = __ldg(&dinv[sa]);
        float4 va = hin[(size_t)sa * 32 + lane];
        acc.x += wa * va.x;
        acc.y += wa * va.y;
        acc.z += wa * va.z;
        acc.w += wa * va.w;
    }
    float sc = -alpha * dinv[w];
    float4 r;
    r.x = sc * acc.x; r.y = sc * acc.y; r.z = sc * acc.z; r.w = sc * acc.w;
    if (sub) {
        float4 u = sub[(size_t)w * 32 + lane];
        r.x -= u.x; r.y -= u.y; r.z -= u.z; r.w -= u.w;
    }
    hout[(size_t)w * 32 + lane] = r;
    // split-image store
    int tile = w >> 7;
    int mloc = w & 127;
    int p = lane >> 4;
    int kk = (lane * 4) & 63;
    split_store4(Ohi, Olo, (size_t)(tile * 2 + p) * 16384, mloc, kk, r.x, r.y, r.z, r.w);
}

// ---------------- final: logit + aux ----------------
__global__ void final_kernel(const float4* __restrict__ hc, const float4* __restrict__ emb,
                             const float* __restrict__ clsW2, const float* __restrict__ clsb2,
                             const float* __restrict__ auxW, const float* __restrict__ auxB,
                             float* __restrict__ out) {
    int t = blockIdx.x * blockDim.x + threadIdx.x;
    int gw = t >> 5;
    int lane = t & 31;
    if (gw >= (RR + 1) * NN) return;
    const float4* vec;
    const float4* wv;
    float b;
    if (gw < NN) {
        vec = hc + (size_t)gw * 32;
        wv = (const float4*)clsW2;
        b = clsb2[0];
    } else {
        int r = (gw - NN) / NN;
        int n = (gw - NN) - r * NN;
        vec = emb + ((size_t)r * NN + n) * 32;
        wv = (const float4*)(auxW + r * HH);
        b = auxB[r];
    }
    float4 a = vec[lane];
    float4 w = wv[lane];
    float s = a.x * w.x + a.y * w.y + a.z * w.z + a.w * w.w;
#pragma unroll
    for (int off = 16; off; off >>= 1) s += __shfl_xor_sync(0xFFFFFFFFu, s, off);
    if (lane == 0) out[gw] = s + b;
}

// ---------------- launch ----------------
extern "C" void kernel_launch(void* const* d_in, const int* in_sizes, int n_in,
                              void* d_out, int out_size) {
    (void)in_sizes; (void)n_in; (void)out_size;
    const float* x     = (const float*)d_in[0];
    const int*   ei    = (const int*)d_in[1];
    const float* chebW = (const float*)d_in[2];
    const float* chebB = (const float*)d_in[3];
    const float* projW = (const float*)d_in[4];
    const float* projB = (const float*)d_in[5];
    const float* W1    = (const float*)d_in[6];
    const float* b1    = (const float*)d_in[7];
    const float* W2    = (const float*)d_in[8];
    const float* b2    = (const float*)d_in[9];
    const float* auxW  = (const float*)d_in[10];
    const float* auxB  = (const float*)d_in[11];
    float* out = (float*)d_out;

    float *emb, *hA, *hB, *tx, *tx2, *dinv;
    int *deg, *cnt, *rp, *cur, *col, *bs;
    __nv_bfloat16 *Bhi, *Blo;
    __nv_bfloat16 *xsh, *xsl, *txh, *txl, *tx2h, *tx2l, *hAh, *hAl, *hBh, *hBl, *esh, *esl;
    cudaGetSymbolAddress((void**)&emb, g_emb);
    cudaGetSymbolAddress((void**)&hA, g_hA);
    cudaGetSymbolAddress((void**)&hB, g_hB);
    cudaGetSymbolAddress((void**)&tx, g_tx);
    cudaGetSymbolAddress((void**)&tx2, g_tx2);
    cudaGetSymbolAddress((void**)&dinv, g_dinv);
    cudaGetSymbolAddress((void**)&deg, g_deg);
    cudaGetSymbolAddress((void**)&cnt, g_cnt);
    cudaGetSymbolAddress((void**)&rp, g_rp);
    cudaGetSymbolAddress((void**)&cur, g_cur);
    cudaGetSymbolAddress((void**)&col, g_col);
    cudaGetSymbolAddress((void**)&bs, g_bsums);
    cudaGetSymbolAddress((void**)&Bhi, g_Bhi);
    cudaGetSymbolAddress((void**)&Blo, g_Blo);
    cudaGetSymbolAddress((void**)&xsh, g_xs_hi);
    cudaGetSymbolAddress((void**)&xsl, g_xs_lo);
    cudaGetSymbolAddress((void**)&txh, g_tx_hi);
    cudaGetSymbolAddress((void**)&txl, g_tx_lo);
    cudaGetSymbolAddress((void**)&tx2h, g_tx2_hi);
    cudaGetSymbolAddress((void**)&tx2l, g_tx2_lo);
    cudaGetSymbolAddress((void**)&hAh, g_hA_hi);
    cudaGetSymbolAddress((void**)&hAl, g_hA_lo);
    cudaGetSymbolAddress((void**)&hBh, g_hB_hi);
    cudaGetSymbolAddress((void**)&hBl, g_hB_lo);
    cudaGetSymbolAddress((void**)&esh, g_es_hi);
    cudaGetSymbolAddress((void**)&esl, g_es_lo);

    const int SMEM_BYTES = 65536;
    cudaFuncSetAttribute(gemm_mma, cudaFuncAttributeMaxDynamicSharedMemorySize, SMEM_BYTES);

    // CSR build
    zero2_kernel<<<(RR * NN + 255) / 256, 256>>>(deg, cnt, RR * NN);
    count_kernel<<<(RR * EE + 255) / 256, 256>>>(ei, deg, cnt);
    dinv_kernel<<<(RR * NN + 255) / 256, 256>>>(deg, dinv);
    const int ntot = RR * NN;
    const int nb = (ntot + 1023) / 1024;
    scan1_kernel<<<nb, 1024>>>(cnt, rp, bs, ntot);
    scan2_kernel<<<1, 512>>>(bs, nb);
    scan3_kernel<<<nb, 1024>>>(rp, bs, cur, ntot, RR * EE);
    fill_kernel<<<(RR * EE + 255) / 256, 256>>>(ei, cur, col);

    // weight preconversion + x split
    preconv_kernel<<<(NCH_TOTAL * 8192 + 255) / 256, 256>>>(chebW, projW, W1, Bhi, Blo);
    xsplit_kernel<<<(NN * 32 + 255) / 256, 256>>>((const float4*)x, xsh, xsl);

    const int propBlocks = (NN * 32 + 255) / 256;
    const int gemmGrid = NT;   // 391

    for (int r = 0; r < RR; r++) {
        const float* h = x;
        const __nv_bfloat16 *hh = xsh, *hl = xsl;
        for (int l = 0; l < LL; l++) {
            prop_kernel<<<propBlocks, 256>>>((const float4*)h, (float4*)tx,
                                             rp + r * NN, col, dinv + r * NN, nullptr, 1.0f,
                                             txh, txl);
            prop_kernel<<<propBlocks, 256>>>((const float4*)tx, (float4*)tx2,
                                             rp + r * NN, col, dinv + r * NN,
                                             (const float4*)h, 2.0f, tx2h, tx2l);
            float* o;
            __nv_bfloat16 *oh, *ol;
            if (l == LL - 1) { o = emb + (size_t)r * NN * HH; oh = esh + (size_t)r * IMG_ELEMS; ol = esl + (size_t)r * IMG_ELEMS; }
            else if (l == 0) { o = hA; oh = hAh; ol = hAl; }
            else             { o = hB; oh = hBh; ol = hBl; }
            Seg s;
            s.hi[0] = hh;  s.lo[0] = hl;
            s.hi[1] = txh; s.lo[1] = txl;
            s.hi[2] = tx2h; s.lo[2] = tx2l;
            for (int i = 3; i < 6; i++) { s.hi[i] = nullptr; s.lo[i] = nullptr; }
            int g = r * LL + l;
            gemm_mma<<<gemmGrid, 256, SMEM_BYTES>>>(s, Bhi + (size_t)(g * 6) * 8192,
                                                    Blo + (size_t)(g * 6) * 8192,
                                                    chebB + (size_t)g * HH, o, oh, ol, 6, 1);
            h = o; hh = oh; hl = ol;
        }
    }

    // hp = relu(concat_r(emb) @ projW + projB): A = emb splits; out split into tx images
    Seg sp;
    for (int r = 0; r < RR; r++) { sp.hi[r] = esh + (size_t)r * IMG_ELEMS; sp.lo[r] = esl + (size_t)r * IMG_ELEMS; }
    gemm_mma<<<gemmGrid, 256, SMEM_BYTES>>>(sp, Bhi + (size_t)108 * 8192,
                                            Blo + (size_t)108 * 8192, projB, hA, txh, txl, 12, 1);

    // hc = relu(hp @ W1 + b1): A = tx images; no split output needed
    Seg s1;
    s1.hi[0] = txh; s1.lo[0] = txl;
    for (int i = 1; i < 6; i++) { s1.hi[i] = nullptr; s1.lo[i] = nullptr; }
    gemm_mma<<<gemmGrid, 256, SMEM_BYTES>>>(s1, Bhi + (size_t)120 * 8192,
                                            Blo + (size_t)120 * 8192, b1, hB,
                                            (__nv_bfloat16*)nullptr, (__nv_bfloat16*)nullptr, 2, 1);

    final_kernel<<<((RR + 1) * NN * 32 + 255) / 256, 256>>>(
        (const float4*)hB, (const float4*)emb, W2, b2, auxW, auxB, out);
}